// round 12
// baseline (speedup 1.0000x reference)
#include <cuda_runtime.h>
#include <cuda_bf16.h>
#include <cstdint>
#include <math.h>

#define BB 4
#define TT 2048
#define CC 1024
#define HH 16
#define HD 64
#define MM (BB*TT)
#define QS 72   // attn smem row stride in bf16 (144B): LDSM-conflict-free

// ---------------- scratch (static device arrays; no cudaMalloc) -------------
__device__ __nv_bfloat16 g_Qh[BB*HH*TT*HD], g_Ql[BB*HH*TT*HD];
__device__ __nv_bfloat16 g_Kh[BB*HH*TT*HD], g_Kl[BB*HH*TT*HD];
__device__ __nv_bfloat16 g_Vh[BB*HH*TT*HD], g_Vl[BB*HH*TT*HD];

__device__ __nv_bfloat16 g_xh[MM*CC],     g_xl[MM*CC];
__device__ __nv_bfloat16 g_wqh[3*CC*CC],  g_wql[3*CC*CC];
__device__ __nv_bfloat16 g_woh[CC*CC],    g_wol[CC*CC];
__device__ __nv_bfloat16 g_ah[MM*CC],     g_al[MM*CC];

extern __shared__ unsigned char dynsm[];

// bf16 mma: D(f32) += A(bf16) * B(bf16)
#define MMA_BF16(acc, a, b) \
    asm("mma.sync.aligned.m16n8k16.row.col.f32.bf16.bf16.f32 " \
        "{%0,%1,%2,%3}, {%4,%5,%6,%7}, {%8,%9}, {%0,%1,%2,%3};" \
        : "+f"((acc)[0]), "+f"((acc)[1]), "+f"((acc)[2]), "+f"((acc)[3]) \
        : "r"((a)[0]), "r"((a)[1]), "r"((a)[2]), "r"((a)[3]), "r"((b)[0]), "r"((b)[1]))

#define LDSM_X4(r, addr) \
    asm volatile("ldmatrix.sync.aligned.m8n8.x4.shared.b16 {%0,%1,%2,%3}, [%4];" \
        : "=r"((r)[0]), "=r"((r)[1]), "=r"((r)[2]), "=r"((r)[3]) : "r"(addr))
#define LDSM_X2(r, addr) \
    asm volatile("ldmatrix.sync.aligned.m8n8.x2.shared.b16 {%0,%1}, [%2];" \
        : "=r"((r)[0]), "=r"((r)[1]) : "r"(addr))
#define LDSM_X4_T(r, addr) \
    asm volatile("ldmatrix.sync.aligned.m8n8.x4.trans.shared.b16 {%0,%1,%2,%3}, [%4];" \
        : "=r"((r)[0]), "=r"((r)[1]), "=r"((r)[2]), "=r"((r)[3]) : "r"(addr))

__device__ __forceinline__ unsigned smem_u32(const void* p) {
    return (unsigned)__cvta_generic_to_shared(p);
}
__device__ __forceinline__ unsigned pack_bf(__nv_bfloat16 lo, __nv_bfloat16 hi) {
    return ((unsigned)__bfloat16_as_ushort(hi) << 16) | __bfloat16_as_ushort(lo);
}

// ---------------------------------------------------------------------------
// split: fp32 -> (hi, lo) bf16. DST bound in device code. 0=x 1=qkv_w 2=out_w
// ---------------------------------------------------------------------------
template<int DST>
__global__ __launch_bounds__(256)
void split_kernel(const float4* __restrict__ src, int n4)
{
    int i = blockIdx.x * blockDim.x + threadIdx.x;
    if (i >= n4) return;
    ushort4* hi; ushort4* lo;
    if      (DST == 0) { hi = (ushort4*)g_xh;  lo = (ushort4*)g_xl;  }
    else if (DST == 1) { hi = (ushort4*)g_wqh; lo = (ushort4*)g_wql; }
    else               { hi = (ushort4*)g_woh; lo = (ushort4*)g_wol; }
    float4 v = src[i];
    ushort4 h, l;
#define SPL(c, hc, lc) { \
        __nv_bfloat16 hb = __float2bfloat16_rn(v.c); \
        __nv_bfloat16 lb = __float2bfloat16_rn(v.c - __bfloat162float(hb)); \
        hc = __bfloat16_as_ushort(hb); lc = __bfloat16_as_ushort(lb); }
    SPL(x, h.x, l.x) SPL(y, h.y, l.y) SPL(z, h.z, l.z) SPL(w, h.w, l.w)
#undef SPL
    hi[i] = h; lo[i] = l;
}

// ---------------------------------------------------------------------------
// Tensor-core GEMM (bf16x3), double-buffered smem.
// Per buffer: sAh|sAl|sBh|sBl, each 128 rows x 20 words (80B stride).
// Byte offsets: arrays at 0/10240/20480/30720; buffer stride 40960. Total 80KB.
// ---------------------------------------------------------------------------
template<int MODE>
__global__ __launch_bounds__(256)
void gemm_bf16(const float* __restrict__ bias, float* __restrict__ out)
{
    unsigned* sm = (unsigned*)dynsm;
    const unsigned smBase = smem_u32(sm);

    const __nv_bfloat16* Ah_g = (MODE == 0) ? g_xh  : g_ah;
    const __nv_bfloat16* Al_g = (MODE == 0) ? g_xl  : g_al;
    const __nv_bfloat16* Bh_g = (MODE == 0) ? g_wqh : g_woh;
    const __nv_bfloat16* Bl_g = (MODE == 0) ? g_wql : g_wol;

    const int tid  = threadIdx.x;
    const int warp = tid >> 5;
    const int lane = tid & 31;
    const int g = lane >> 2;
    const int t = lane & 3;
    const int wm = (warp & 1) * 64;
    const int wn = (warp >> 1) * 32;
    const int m0 = blockIdx.y * 128;
    const int n0 = blockIdx.x * 128;

    const int lrow = tid >> 1;
    const int loff = (tid & 1) * 8;

    const __nv_bfloat16* Ap  = Ah_g + (size_t)(m0 + lrow) * CC + loff * 2;
    const __nv_bfloat16* Alp = Al_g + (size_t)(m0 + lrow) * CC + loff * 2;
    const __nv_bfloat16* Bp  = Bh_g + (size_t)(n0 + lrow) * CC + loff * 2;
    const __nv_bfloat16* Blp = Bl_g + (size_t)(n0 + lrow) * CC + loff * 2;

    const unsigned aOff = (unsigned)(wm + (lane & 15)) * 80u + (unsigned)(lane >> 4) * 16u;
    const unsigned bOff = (unsigned)(wn + (lane & 7))  * 80u + (unsigned)((lane >> 3) & 1) * 16u;
    const int srow = lrow * 20 + loff;     // word offset of this thread's store

    float acc[4][4][4];
    #pragma unroll
    for (int i = 0; i < 4; ++i)
        #pragma unroll
        for (int j = 0; j < 4; ++j)
            #pragma unroll
            for (int e = 0; e < 4; ++e) acc[i][j][e] = 0.f;

    uint4 rah0, rah1, ral0, ral1, rbh0, rbh1, rbl0, rbl1;
#define LOAD_STAGE(kt) { \
        const int eo = (kt) * 32; \
        rah0 = *(const uint4*)(Ap  + eo); rah1 = *(const uint4*)(Ap  + eo + 8); \
        ral0 = *(const uint4*)(Alp + eo); ral1 = *(const uint4*)(Alp + eo + 8); \
        rbh0 = *(const uint4*)(Bp  + eo); rbh1 = *(const uint4*)(Bp  + eo + 8); \
        rbl0 = *(const uint4*)(Blp + eo); rbl1 = *(const uint4*)(Blp + eo + 8); }

#define STORE_STAGE(bufsel) { \
        unsigned* bw = sm + (bufsel) * 10240; \
        *(uint4*)(bw + srow)         = rah0; *(uint4*)(bw + srow + 4)         = rah1; \
        *(uint4*)(bw + 2560 + srow)  = ral0; *(uint4*)(bw + 2560 + srow + 4)  = ral1; \
        *(uint4*)(bw + 5120 + srow)  = rbh0; *(uint4*)(bw + 5120 + srow + 4)  = rbh1; \
        *(uint4*)(bw + 7680 + srow)  = rbl0; *(uint4*)(bw + 7680 + srow + 4)  = rbl1; }

    LOAD_STAGE(0);
    STORE_STAGE(0);
    __syncthreads();

    int buf = 0;
    #pragma unroll 1
    for (int kt = 0; kt < 32; ++kt) {
        if (kt + 1 < 32) LOAD_STAGE(kt + 1);

        const unsigned bb = smBase + (unsigned)buf * 40960u;
        const unsigned baseAh = bb + aOff;
        const unsigned baseAl = bb + 10240u + aOff;
        const unsigned baseBh = bb + 20480u + bOff;
        const unsigned baseBl = bb + 30720u + bOff;

        #pragma unroll
        for (int ks = 0; ks < 2; ++ks) {
            const unsigned ko = (unsigned)ks * 32u;

            unsigned ah[4][4], al[4][4], bh[4][2], bl[4][2];
            #pragma unroll
            for (int mt = 0; mt < 4; ++mt) {
                LDSM_X4(ah[mt], baseAh + (unsigned)mt * 1280u + ko);
                LDSM_X4(al[mt], baseAl + (unsigned)mt * 1280u + ko);
            }
            #pragma unroll
            for (int nt = 0; nt < 4; ++nt) {
                LDSM_X2(bh[nt], baseBh + (unsigned)nt * 640u + ko);
                LDSM_X2(bl[nt], baseBl + (unsigned)nt * 640u + ko);
            }
            #pragma unroll
            for (int mt = 0; mt < 4; ++mt)
                #pragma unroll
                for (int nt = 0; nt < 4; ++nt) {
                    MMA_BF16(acc[mt][nt], ah[mt], bh[nt]);
                    MMA_BF16(acc[mt][nt], ah[mt], bl[nt]);
                    MMA_BF16(acc[mt][nt], al[mt], bh[nt]);
                }
        }

        if (kt + 1 < 32) {
            STORE_STAGE(buf ^ 1);
            __syncthreads();
            buf ^= 1;
        }
    }

    #pragma unroll
    for (int mt = 0; mt < 4; ++mt)
        #pragma unroll
        for (int nt = 0; nt < 4; ++nt)
            #pragma unroll
            for (int i = 0; i < 4; ++i) {
                const int m = m0 + wm + mt * 16 + g + (i >> 1) * 8;
                const int n = n0 + wn + nt * 8 + t * 2 + (i & 1);
                float v = acc[mt][nt][i] + bias[n];
                if (MODE == 0) {
                    const int which = n >> 10;          // 0=q 1=k 2=v
                    const int hc = n & 1023;
                    const int h  = hc >> 6;
                    const int d  = hc & 63;
                    const int b  = m >> 11;
                    const int tt = m & (TT - 1);
                    __nv_bfloat16* dh = (which == 0) ? g_Qh : (which == 1) ? g_Kh : g_Vh;
                    __nv_bfloat16* dl = (which == 0) ? g_Ql : (which == 1) ? g_Kl : g_Vl;
                    if (which == 0) v *= 0.125f;        // 1/sqrt(64)
                    __nv_bfloat16 hb = __float2bfloat16_rn(v);
                    __nv_bfloat16 lb = __float2bfloat16_rn(v - __bfloat162float(hb));
                    const size_t off = (size_t)((b*HH + h)*TT + tt) * HD + d;
                    dh[off] = hb; dl[off] = lb;
                } else {
                    out[(size_t)m * CC + n] = v;
                }
            }
}

// ---------------------------------------------------------------------------
// Tensor-core causal flash attention (bf16x3), separate K and V buffers.
// dynsm layout (bytes): QH 0, QL 9216, KH 18432, KL 27648, VH 36864, VL 46080
// Total 54KB. 2 syncs per KV tile (was 4).
// ---------------------------------------------------------------------------
__global__ __launch_bounds__(128)
void attn_mma()
{
    __nv_bfloat16* sQh = (__nv_bfloat16*)(dynsm);
    __nv_bfloat16* sQl = (__nv_bfloat16*)(dynsm +  9216);
    __nv_bfloat16* sKh = (__nv_bfloat16*)(dynsm + 18432);
    __nv_bfloat16* sKl = (__nv_bfloat16*)(dynsm + 27648);
    __nv_bfloat16* sVh = (__nv_bfloat16*)(dynsm + 36864);
    __nv_bfloat16* sVl = (__nv_bfloat16*)(dynsm + 46080);

    const int tid  = threadIdx.x;
    const int warp = tid >> 5;
    const int lane = tid & 31;
    const int g = lane >> 2;
    const int t = lane & 3;
    const int q0 = blockIdx.x * 64;
    const int bh = blockIdx.y;
    const size_t gbase = (size_t)bh * TT * HD;

    // Q tile -> smem
    #pragma unroll
    for (int idx = tid; idx < 512; idx += 128) {
        const int r = idx >> 3, c = idx & 7;
        const size_t go = gbase + (size_t)(q0 + r) * HD + c * 8;
        *(uint4*)&sQh[r*QS + c*8] = *(const uint4*)&g_Qh[go];
        *(uint4*)&sQl[r*QS + c*8] = *(const uint4*)&g_Ql[go];
    }

    const unsigned qOff = (unsigned)(warp*16 + (lane & 15)) * 144u + (unsigned)(lane >> 4) * 16u;
    const unsigned kOff = (unsigned)(((lane >> 4) & 1) * 8 + (lane & 7)) * 144u
                        + (unsigned)((lane >> 3) & 1) * 16u;
    const unsigned vOff = (unsigned)(((lane >> 3) & 1) * 8 + (lane & 7)) * 144u
                        + (unsigned)((lane >> 4) & 1) * 16u;
    const unsigned qbh = smem_u32(sQh) + qOff, qbl = smem_u32(sQl) + qOff;
    const unsigned kbh = smem_u32(sKh) + kOff, kbl = smem_u32(sKl) + kOff;
    const unsigned vbh = smem_u32(sVh) + vOff, vbl = smem_u32(sVl) + vOff;

    float m_i[2] = {-1e30f, -1e30f}, l_i[2] = {0.f, 0.f};
    float oacc[8][4];
    #pragma unroll
    for (int i = 0; i < 8; ++i)
        #pragma unroll
        for (int e = 0; e < 4; ++e) oacc[i][e] = 0.f;

    #pragma unroll 1
    for (int j0 = 0; j0 <= q0; j0 += 64) {
        // ---- K and V tiles together ----
        #pragma unroll
        for (int idx = tid; idx < 512; idx += 128) {
            const int r = idx >> 3, c = idx & 7;
            const size_t go = gbase + (size_t)(j0 + r) * HD + c * 8;
            *(uint4*)&sKh[r*QS + c*8] = *(const uint4*)&g_Kh[go];
            *(uint4*)&sKl[r*QS + c*8] = *(const uint4*)&g_Kl[go];
            *(uint4*)&sVh[r*QS + c*8] = *(const uint4*)&g_Vh[go];
            *(uint4*)&sVl[r*QS + c*8] = *(const uint4*)&g_Vl[go];
        }
        __syncthreads();

        // ---- S = Q K^T ----
        float sacc[8][4];
        #pragma unroll
        for (int i = 0; i < 8; ++i)
            #pragma unroll
            for (int e = 0; e < 4; ++e) sacc[i][e] = 0.f;

        #pragma unroll
        for (int kc = 0; kc < 4; ++kc) {
            unsigned qh[4], ql[4];
            LDSM_X4(qh, qbh + kc*32u);
            LDSM_X4(ql, qbl + kc*32u);
            #pragma unroll
            for (int ntp = 0; ntp < 4; ++ntp) {
                unsigned kh[4], kl[4];
                LDSM_X4(kh, kbh + (unsigned)ntp*2304u + kc*32u);
                LDSM_X4(kl, kbl + (unsigned)ntp*2304u + kc*32u);
                MMA_BF16(sacc[2*ntp],   qh, kh);
                MMA_BF16(sacc[2*ntp],   qh, kl);
                MMA_BF16(sacc[2*ntp],   ql, kh);
                MMA_BF16(sacc[2*ntp+1], qh, kh + 2);
                MMA_BF16(sacc[2*ntp+1], qh, kl + 2);
                MMA_BF16(sacc[2*ntp+1], ql, kh + 2);
            }
        }

        // ---- causal mask (diagonal tile only) ----
        if (j0 == q0) {
            const int rbase = q0 + warp*16;
            #pragma unroll
            for (int nt = 0; nt < 8; ++nt)
                #pragma unroll
                for (int e = 0; e < 4; ++e) {
                    const int col = j0 + nt*8 + t*2 + (e & 1);
                    const int row = rbase + g + (e >> 1)*8;
                    if (col > row) sacc[nt][e] = -1e30f;
                }
        }

        // ---- online softmax ----
        #pragma unroll
        for (int h2 = 0; h2 < 2; ++h2) {
            float mloc = -1e30f;
            #pragma unroll
            for (int nt = 0; nt < 8; ++nt)
                mloc = fmaxf(mloc, fmaxf(sacc[nt][2*h2], sacc[nt][2*h2+1]));
            mloc = fmaxf(mloc, __shfl_xor_sync(0xffffffffu, mloc, 1));
            mloc = fmaxf(mloc, __shfl_xor_sync(0xffffffffu, mloc, 2));
            const float mnew = fmaxf(m_i[h2], mloc);
            const float corr = __expf(m_i[h2] - mnew);
            float sum = 0.f;
            #pragma unroll
            for (int nt = 0; nt < 8; ++nt) {
                const float p0 = __expf(sacc[nt][2*h2]   - mnew);
                const float p1 = __expf(sacc[nt][2*h2+1] - mnew);
                sacc[nt][2*h2] = p0; sacc[nt][2*h2+1] = p1;
                sum += p0 + p1;
            }
            sum += __shfl_xor_sync(0xffffffffu, sum, 1);
            sum += __shfl_xor_sync(0xffffffffu, sum, 2);
            l_i[h2] = l_i[h2] * corr + sum;
            m_i[h2] = mnew;
            #pragma unroll
            for (int dt = 0; dt < 8; ++dt) {
                oacc[dt][2*h2] *= corr; oacc[dt][2*h2+1] *= corr;
            }
        }

        // ---- O += P V ----
        #pragma unroll
        for (int kc = 0; kc < 4; ++kc) {
            unsigned ph[4], pl[4];
            #pragma unroll
            for (int u = 0; u < 4; ++u) {
                const int nt = 2*kc + (u >> 1);
                const float a0 = sacc[nt][(u & 1)*2], a1 = sacc[nt][(u & 1)*2 + 1];
                const __nv_bfloat16 h0 = __float2bfloat16_rn(a0);
                const __nv_bfloat16 h1 = __float2bfloat16_rn(a1);
                ph[u] = pack_bf(h0, h1);
                pl[u] = pack_bf(__float2bfloat16_rn(a0 - __bfloat162float(h0)),
                                __float2bfloat16_rn(a1 - __bfloat162float(h1)));
            }
            #pragma unroll
            for (int dtp = 0; dtp < 4; ++dtp) {
                unsigned vh[4], vl[4];
                LDSM_X4_T(vh, vbh + (unsigned)kc*2304u + dtp*32u);
                LDSM_X4_T(vl, vbl + (unsigned)kc*2304u + dtp*32u);
                MMA_BF16(oacc[2*dtp],   ph, vh);
                MMA_BF16(oacc[2*dtp],   ph, vl);
                MMA_BF16(oacc[2*dtp],   pl, vh);
                MMA_BF16(oacc[2*dtp+1], ph, vh + 2);
                MMA_BF16(oacc[2*dtp+1], ph, vl + 2);
                MMA_BF16(oacc[2*dtp+1], pl, vh + 2);
            }
        }
        __syncthreads();   // PV reads done before next K/V store
    }

    // ---- epilogue: normalize, split to bf16 h/l, merge heads ----
    const int b  = bh >> 4;
    const int hh = bh & 15;
    #pragma unroll
    for (int h2 = 0; h2 < 2; ++h2) {
        const float inv = 1.f / l_i[h2];
        const int r = q0 + warp*16 + g + h2*8;
        const size_t rowoff = (size_t)(b*TT + r) * CC + hh*HD;
        #pragma unroll
        for (int dt = 0; dt < 8; ++dt) {
            const float o0 = oacc[dt][2*h2] * inv;
            const float o1 = oacc[dt][2*h2+1] * inv;
            const __nv_bfloat16 h0 = __float2bfloat16_rn(o0);
            const __nv_bfloat16 h1 = __float2bfloat16_rn(o1);
            const unsigned wh = pack_bf(h0, h1);
            const unsigned wl = pack_bf(__float2bfloat16_rn(o0 - __bfloat162float(h0)),
                                        __float2bfloat16_rn(o1 - __bfloat162float(h1)));
            *(unsigned*)&g_ah[rowoff + dt*8 + t*2] = wh;
            *(unsigned*)&g_al[rowoff + dt*8 + t*2] = wl;
        }
    }
}

// ---------------------------------------------------------------------------
extern "C" void kernel_launch(void* const* d_in, const int* in_sizes, int n_in,
                              void* d_out, int out_size)
{
    const float* x     = (const float*)d_in[0];
    const float* qkv_b = (const float*)d_in[2];
    const float* out_b = (const float*)d_in[4];
    float* y = (float*)d_out;

    cudaFuncSetAttribute(gemm_bf16<0>, cudaFuncAttributeMaxDynamicSharedMemorySize, 81920);
    cudaFuncSetAttribute(gemm_bf16<1>, cudaFuncAttributeMaxDynamicSharedMemorySize, 81920);
    cudaFuncSetAttribute(attn_mma,     cudaFuncAttributeMaxDynamicSharedMemorySize, 55296);

    {
        int n4 = MM*CC/4;
        split_kernel<0><<<(n4+255)/256, 256>>>((const float4*)x, n4);
    }
    {
        int n4 = 3*CC*CC/4;
        split_kernel<1><<<(n4+255)/256, 256>>>((const float4*)d_in[1], n4);
    }
    {
        int n4 = CC*CC/4;
        split_kernel<2><<<(n4+255)/256, 256>>>((const float4*)d_in[3], n4);
    }

    // 1) QKV projection -> Q/K/V bf16 hi/lo
    gemm_bf16<0><<<dim3(3*CC/128, MM/128), 256, 81920>>>(qkv_b, nullptr);
    // 2) causal attention (tensor cores) -> g_ah/g_al
    attn_mma<<<dim3(TT/64, BB*HH), 128, 55296>>>();
    // 3) output projection
    gemm_bf16<1><<<dim3(CC/128, MM/128), 256, 81920>>>(out_b, y);
}